// round 4
// baseline (speedup 1.0000x reference)
#include <cuda_runtime.h>
#include <math.h>

#define NUM_LEVELS 16
#define TABLE_SIZE (1u << 19)
#define TSAMP 192
#define PTS 128            // points per block
#define NTHREADS 256
#define FS2 68             // feats row stride in float2: 68%16==4 -> (4r+c)%16 bijective
#define WS2 68             // W0   row stride in float2: (4c+r)%16 bijective

struct LevelParams {
    float scale[NUM_LEVELS];
    int   res[NUM_LEVELS];
    unsigned hashed_mask;
};

__device__ __forceinline__ float f2tf32f(float v) {
    unsigned r;
    asm("cvt.rna.tf32.f32 %0, %1;" : "=r"(r) : "f"(v));
    return __uint_as_float(r);
}

__device__ __forceinline__ float softplus10(float v) {
    float y = 10.0f * v;
    float t = __expf(-fabsf(y));
    return (fmaxf(y, 0.0f) + __logf(1.0f + t)) * 0.1f;
}

#define MMA_TF32(C, A0, A1, A2, A3, B0, B1)                                    \
    asm volatile(                                                              \
        "mma.sync.aligned.m16n8k8.row.col.f32.tf32.tf32.f32 "                  \
        "{%0,%1,%2,%3}, {%4,%5,%6,%7}, {%8,%9}, {%0,%1,%2,%3};"                \
        : "+f"(C[0]), "+f"(C[1]), "+f"(C[2]), "+f"(C[3])                       \
        : "r"(A0), "r"(A1), "r"(A2), "r"(A3), "r"(B0), "r"(B1));

__global__ __launch_bounds__(NTHREADS, 2)
void nerf_fused(const float* __restrict__ x,
                const float4* __restrict__ emb,
                const float* __restrict__ W0,
                const float* __restrict__ b0,
                const float* __restrict__ W1,
                const float* __restrict__ b1,
                float* __restrict__ out,
                LevelParams lp)
{
    extern __shared__ float sm[];
    float2* sF2 = (float2*)sm;                 // [PTS][FS2]   {hi,lo} feats
    float2* sW2 = sF2 + PTS * FS2;             // [64][WS2]    {hi,lo} W0
    float*  sb0 = (float*)(sW2 + 64 * WS2);    // [64]
    float*  sW1 = sb0 + 64;                    // [64]
    float*  sb1 = sW1 + 64;                    // [1]

    const int tid = threadIdx.x;

    // ---- W0 split into interleaved {tf32-hi, tf32-lo} ----
    for (int e = tid; e < 4096; e += NTHREADS) {
        int k = e >> 6, n = e & 63;
        float w  = W0[e];
        float hi = f2tf32f(w);
        float lo = f2tf32f(w - hi);
        sW2[k * WS2 + n] = make_float2(hi, lo);
    }
    if (tid < 64) { sb0[tid] = b0[tid]; sW1[tid] = W1[tid]; }
    if (tid == 0) { sb1[0] = b1[0]; }

    // ---- Phase 1: hash-grid gather; 2 threads per point (8 levels each) ----
    const int pt   = tid & (PTS - 1);
    const int half = tid >> 7;                  // levels [0..7] or [8..15]
    const int p    = blockIdx.x * PTS + pt;
    const int ray  = p / TSAMP;
    const int t    = p - ray * TSAMP;

    const float2* xr = (const float2*)(x + (size_t)ray * (TSAMP * 2));
    float2 o  = xr[0];
    float2 en = xr[TSAMP - 1];
    float dxr = en.x - o.x, dyr = en.y - o.y;
    float nrm = sqrtf(dxr * dxr + dyr * dyr);
    dxr /= nrm; dyr /= nrm;

    const float step = 2.0f / 191.0f;
    float z  = step * (float)t;
    float ux = (fminf(fmaxf(o.x + dxr * z, -1.0f), 1.0f) + 1.0f) * 0.5f;
    float uy = (fminf(fmaxf(o.y + dyr * z, -1.0f), 1.0f) + 1.0f) * 0.5f;

    float2* frow = sF2 + pt * FS2 + half * 32;  // k = half*32 + l2*4 + d
    #pragma unroll
    for (int l2 = 0; l2 < 8; ++l2) {
        int l = (half << 3) + l2;
        float s = lp.scale[l];
        float posx = ux * s + 0.5f;
        float posy = uy * s + 0.5f;
        float pfx = floorf(posx), pfy = floorf(posy);
        float frx = posx - pfx,   fry = posy - pfy;
        int ix = (int)pfx, iy = (int)pfy;

        unsigned i00, i01, i10, i11;
        if (lp.hashed_mask & (1u << l)) {
            unsigned hy0 = (unsigned)iy * 2654435761u;
            unsigned hy1 = (unsigned)(iy + 1) * 2654435761u;
            i00 = ((unsigned)ix       ^ hy0) & (TABLE_SIZE - 1u);
            i01 = ((unsigned)ix       ^ hy1) & (TABLE_SIZE - 1u);
            i10 = ((unsigned)(ix + 1) ^ hy0) & (TABLE_SIZE - 1u);
            i11 = ((unsigned)(ix + 1) ^ hy1) & (TABLE_SIZE - 1u);
        } else {
            int res = lp.res[l];
            i00 = (unsigned)(iy * res + ix);
            i01 = i00 + (unsigned)res;
            i10 = i00 + 1u;
            i11 = i01 + 1u;
        }

        const float4* tab = emb + (size_t)l * TABLE_SIZE;
        float4 c00 = __ldg(tab + i00);
        float4 c01 = __ldg(tab + i01);
        float4 c10 = __ldg(tab + i10);
        float4 c11 = __ldg(tab + i11);

        float w00 = (1.0f - frx) * (1.0f - fry);
        float w01 = (1.0f - frx) * fry;
        float w10 = frx * (1.0f - fry);
        float w11 = frx * fry;

        float4 f4;
        f4.x = ((c00.x * w00 + c01.x * w01) + c10.x * w10) + c11.x * w11;
        f4.y = ((c00.y * w00 + c01.y * w01) + c10.y * w10) + c11.y * w11;
        f4.z = ((c00.z * w00 + c01.z * w01) + c10.z * w10) + c11.z * w11;
        f4.w = ((c00.w * w00 + c01.w * w01) + c10.w * w10) + c11.w * w11;

        // split each feature into {tf32-hi, tf32-lo}, store interleaved
        float hx = f2tf32f(f4.x), lx = f2tf32f(f4.x - hx);
        float hy = f2tf32f(f4.y), ly = f2tf32f(f4.y - hy);
        float hz = f2tf32f(f4.z), lz = f2tf32f(f4.z - hz);
        float hw = f2tf32f(f4.w), lw = f2tf32f(f4.w - hw);
        float4* dst = (float4*)(frow + l2 * 4);
        dst[0] = make_float4(hx, lx, hy, ly);
        dst[1] = make_float4(hz, lz, hw, lw);
    }

    __syncthreads();

    // ---- Phase 2: per-warp m16n8k8 tf32 GEMM (pre-split, 3 passes) ----
    const int warp = tid >> 5;
    const int lane = tid & 31;
    const int r = lane >> 2;          // 0..7
    const int c = lane & 3;           // 0..3

    float C[8][4];
    #pragma unroll
    for (int nt = 0; nt < 8; ++nt) {
        C[nt][0] = 0.f; C[nt][1] = 0.f; C[nt][2] = 0.f; C[nt][3] = 0.f;
    }

    const float2* Ab = sF2 + (warp * 16) * FS2;
    #pragma unroll
    for (int kk = 0; kk < 8; ++kk) {
        int kb = kk * 8;
        float2 a0 = Ab[r * FS2 + kb + c];
        float2 a1 = Ab[(r + 8) * FS2 + kb + c];
        float2 a2 = Ab[r * FS2 + kb + c + 4];
        float2 a3 = Ab[(r + 8) * FS2 + kb + c + 4];
        unsigned ah0 = __float_as_uint(a0.x), al0 = __float_as_uint(a0.y);
        unsigned ah1 = __float_as_uint(a1.x), al1 = __float_as_uint(a1.y);
        unsigned ah2 = __float_as_uint(a2.x), al2 = __float_as_uint(a2.y);
        unsigned ah3 = __float_as_uint(a3.x), al3 = __float_as_uint(a3.y);

        const float2* Brow0 = sW2 + (kb + c) * WS2;
        const float2* Brow4 = sW2 + (kb + c + 4) * WS2;
        #pragma unroll
        for (int nt = 0; nt < 8; ++nt) {
            int n = nt * 8 + r;
            float2 bv0 = Brow0[n];
            float2 bv1 = Brow4[n];
            unsigned bh0 = __float_as_uint(bv0.x), bl0 = __float_as_uint(bv0.y);
            unsigned bh1 = __float_as_uint(bv1.x), bl1 = __float_as_uint(bv1.y);
            MMA_TF32(C[nt], ah0, ah1, ah2, ah3, bh0, bh1);
            MMA_TF32(C[nt], ah0, ah1, ah2, ah3, bl0, bl1);
            MMA_TF32(C[nt], al0, al1, al2, al3, bh0, bh1);
        }
    }

    // ---- Epilogue: softplus(h)·W1, reduce over cols, density out ----
    float sig0 = 0.f, sig1 = 0.f;
    #pragma unroll
    for (int nt = 0; nt < 8; ++nt) {
        int col0 = nt * 8 + 2 * c;
        int col1 = col0 + 1;
        float b0a = sb0[col0], b0b = sb0[col1];
        float w1a = sW1[col0], w1b = sW1[col1];
        sig0 += softplus10(C[nt][0] + b0a) * w1a;
        sig0 += softplus10(C[nt][1] + b0b) * w1b;
        sig1 += softplus10(C[nt][2] + b0a) * w1a;
        sig1 += softplus10(C[nt][3] + b0b) * w1b;
    }
    sig0 += __shfl_xor_sync(0xffffffffu, sig0, 1);
    sig0 += __shfl_xor_sync(0xffffffffu, sig0, 2);
    sig1 += __shfl_xor_sync(0xffffffffu, sig1, 1);
    sig1 += __shfl_xor_sync(0xffffffffu, sig1, 2);

    if (c == 0) {
        float b1v = sb1[0];
        #pragma unroll
        for (int hrow = 0; hrow < 2; ++hrow) {
            int local = warp * 16 + r + hrow * 8;
            int pp = blockIdx.x * PTS + local;
            int rr = pp / TSAMP;
            int tt = pp - rr * TSAMP;
            float sigv  = (hrow == 0) ? sig0 : sig1;
            float sigma = softplus10(b1v + sigv);
            float zt  = step * (float)tt;
            float zt1 = step * (float)(tt - 1);
            float delta = (tt == 0) ? (1.0f / 192.0f) : (zt - zt1);
            out[pp] = delta * sigma;
        }
    }
}

extern "C" void kernel_launch(void* const* d_in, const int* in_sizes, int n_in,
                              void* d_out, int out_size) {
    const float* x   = (const float*)d_in[0];   // [4,2048,192,2]
    const float* emb = (const float*)d_in[1];   // [16, 524288, 4]
    const float* W0  = (const float*)d_in[2];   // [64,64]
    const float* b0  = (const float*)d_in[3];   // [64]
    const float* W1  = (const float*)d_in[4];   // [64,1]
    const float* b1  = (const float*)d_in[5];   // [1]
    float* out = (float*)d_out;

    LevelParams lp;
    const double b = exp((log(2048.0) - log(2.0)) / 15.0);
    unsigned mask = 0;
    for (int l = 0; l < NUM_LEVELS; ++l) {
        double s = 2.0 * pow(b, (double)l) - 1.0;
        lp.scale[l] = (float)s;
        int res = (int)ceil(s) + 1;
        lp.res[l] = res;
        if ((long long)res * (long long)res > (long long)TABLE_SIZE)
            mask |= (1u << l);
    }
    lp.hashed_mask = mask;

    const int smem_bytes = (PTS * FS2 + 64 * WS2) * 8 + (64 + 64 + 4) * 4;
    static int attr_set = 0;
    if (!attr_set) {
        cudaFuncSetAttribute(nerf_fused,
                             cudaFuncAttributeMaxDynamicSharedMemorySize,
                             smem_bytes);
        attr_set = 1;
    }

    int n_points = in_sizes[0] / 2;             // 1,572,864
    int n_blocks = n_points / PTS;              // 12288
    nerf_fused<<<n_blocks, NTHREADS, smem_bytes>>>(x, (const float4*)emb,
                                                   W0, b0, W1, b1, out, lp);
}

// round 5
// speedup vs baseline: 1.4571x; 1.4571x over previous
#include <cuda_runtime.h>
#include <cuda_bf16.h>
#include <math.h>

#define NUM_LEVELS 16
#define TABLE_SIZE (1u << 19)
#define TSAMP 192
#define PTS 128            // points per block
#define NTHREADS 256
#define FSU 36             // feats plane row stride, u32 units: (4r+c)%32 bijective
#define WSU 72             // W plane row stride, u32 units:    (8c+r)%32 bijective

struct LevelParams {
    float scale[NUM_LEVELS];
    int   res[NUM_LEVELS];
    unsigned hashed_mask;
};

__device__ __forceinline__ float softplus10(float v) {
    float y = 10.0f * v;
    float t = __expf(-fabsf(y));
    return (fmaxf(y, 0.0f) + __logf(1.0f + t)) * 0.1f;
}

__device__ __forceinline__ unsigned pack_bf16x2(float lo_val, float hi_val) {
    // returns reg with lo_val in low 16 bits (element k), hi_val in high (k+1)
    unsigned r;
    asm("cvt.rn.bf16x2.f32 %0, %1, %2;" : "=r"(r) : "f"(hi_val), "f"(lo_val));
    return r;
}

__device__ __forceinline__ float bf16lo_f(unsigned p) {
    return __bfloat162float(__ushort_as_bfloat16((unsigned short)(p & 0xffffu)));
}
__device__ __forceinline__ float bf16hi_f(unsigned p) {
    return __bfloat162float(__ushort_as_bfloat16((unsigned short)(p >> 16)));
}

#define MMA_BF16(C, A0, A1, A2, A3, B0, B1)                                    \
    asm volatile(                                                              \
        "mma.sync.aligned.m16n8k16.row.col.f32.bf16.bf16.f32 "                 \
        "{%0,%1,%2,%3}, {%4,%5,%6,%7}, {%8,%9}, {%0,%1,%2,%3};"                \
        : "+f"(C[0]), "+f"(C[1]), "+f"(C[2]), "+f"(C[3])                       \
        : "r"(A0), "r"(A1), "r"(A2), "r"(A3), "r"(B0), "r"(B1));

__global__ __launch_bounds__(NTHREADS, 2)
void nerf_fused(const float* __restrict__ x,
                const float4* __restrict__ emb,
                const float* __restrict__ W0,
                const float* __restrict__ b0,
                const float* __restrict__ W1,
                const float* __restrict__ b1,
                float* __restrict__ out,
                LevelParams lp)
{
    extern __shared__ unsigned smu[];
    unsigned* FH = smu;                        // [PTS][FSU]  bf16x2 hi feats
    unsigned* FL = FH + PTS * FSU;             // [PTS][FSU]  bf16x2 lo feats
    unsigned* BH = FL + PTS * FSU;             // [32][WSU]   bf16x2 hi W0 (k-pairs x n)
    unsigned* BL = BH + 32 * WSU;              // [32][WSU]
    float*   sb0 = (float*)(BL + 32 * WSU);    // [64]
    float*   sW1 = sb0 + 64;                   // [64]
    float*   sb1 = sW1 + 64;                   // [1]

    const int tid = threadIdx.x;

    // ---- W0 -> bf16 {hi,lo} planes, packed over k-pairs ----
    for (int e = tid; e < 2048; e += NTHREADS) {
        int k2 = e >> 6, n = e & 63;
        float w0v = W0[(2 * k2) * 64 + n];
        float w1v = W0[(2 * k2 + 1) * 64 + n];
        float h0f = __bfloat162float(__float2bfloat16(w0v));
        float h1f = __bfloat162float(__float2bfloat16(w1v));
        BH[k2 * WSU + n] = pack_bf16x2(h0f, h1f);
        BL[k2 * WSU + n] = pack_bf16x2(w0v - h0f, w1v - h1f);
    }
    if (tid < 64) { sb0[tid] = b0[tid]; sW1[tid] = W1[tid]; }
    if (tid == 0) { sb1[0] = b1[0]; }

    // ---- Phase 1: gather; 2 threads/point, interleaved levels ----
    const int pt   = tid & (PTS - 1);
    const int half = tid >> 7;                  // even levels or odd levels
    const int p    = blockIdx.x * PTS + pt;
    const int ray  = p / TSAMP;
    const int t    = p - ray * TSAMP;

    const float2* xr = (const float2*)(x + (size_t)ray * (TSAMP * 2));
    float2 o  = xr[0];
    float2 en = xr[TSAMP - 1];
    float dxr = en.x - o.x, dyr = en.y - o.y;
    float nrm = sqrtf(dxr * dxr + dyr * dyr);
    dxr /= nrm; dyr /= nrm;

    const float step = 2.0f / 191.0f;
    float z  = step * (float)t;
    float ux = (fminf(fmaxf(o.x + dxr * z, -1.0f), 1.0f) + 1.0f) * 0.5f;
    float uy = (fminf(fmaxf(o.y + dyr * z, -1.0f), 1.0f) + 1.0f) * 0.5f;

    unsigned* fh_row = FH + pt * FSU;
    unsigned* fl_row = FL + pt * FSU;
    #pragma unroll
    for (int l2 = 0; l2 < 8; ++l2) {
        int l = 2 * l2 + half;                  // interleaved level assignment
        float s = lp.scale[l];
        float posx = ux * s + 0.5f;
        float posy = uy * s + 0.5f;
        float pfx = floorf(posx), pfy = floorf(posy);
        float frx = posx - pfx,   fry = posy - pfy;
        int ix = (int)pfx, iy = (int)pfy;

        unsigned i00, i01, i10, i11;
        if ((lp.hashed_mask >> l) & 1u) {
            unsigned hy0 = (unsigned)iy * 2654435761u;
            unsigned hy1 = (unsigned)(iy + 1) * 2654435761u;
            i00 = ((unsigned)ix       ^ hy0) & (TABLE_SIZE - 1u);
            i01 = ((unsigned)ix       ^ hy1) & (TABLE_SIZE - 1u);
            i10 = ((unsigned)(ix + 1) ^ hy0) & (TABLE_SIZE - 1u);
            i11 = ((unsigned)(ix + 1) ^ hy1) & (TABLE_SIZE - 1u);
        } else {
            int res = lp.res[l];
            i00 = (unsigned)(iy * res + ix);
            i01 = i00 + (unsigned)res;
            i10 = i00 + 1u;
            i11 = i01 + 1u;
        }

        const float4* tab = emb + (size_t)l * TABLE_SIZE;
        float4 c00 = __ldg(tab + i00);
        float4 c01 = __ldg(tab + i01);
        float4 c10 = __ldg(tab + i10);
        float4 c11 = __ldg(tab + i11);

        float w00 = (1.0f - frx) * (1.0f - fry);
        float w01 = (1.0f - frx) * fry;
        float w10 = frx * (1.0f - fry);
        float w11 = frx * fry;

        float f0 = ((c00.x * w00 + c01.x * w01) + c10.x * w10) + c11.x * w11;
        float f1 = ((c00.y * w00 + c01.y * w01) + c10.y * w10) + c11.y * w11;
        float f2 = ((c00.z * w00 + c01.z * w01) + c10.z * w10) + c11.z * w11;
        float f3 = ((c00.w * w00 + c01.w * w01) + c10.w * w10) + c11.w * w11;

        // split to bf16 hi/lo, pack k-pairs
        float h0 = __bfloat162float(__float2bfloat16(f0));
        float h1 = __bfloat162float(__float2bfloat16(f1));
        float h2 = __bfloat162float(__float2bfloat16(f2));
        float h3 = __bfloat162float(__float2bfloat16(f3));

        int k2 = l * 2;                         // u32 index of feat pair (k=4l..4l+3)
        fh_row[k2 + 0] = pack_bf16x2(h0, h1);
        fh_row[k2 + 1] = pack_bf16x2(h2, h3);
        fl_row[k2 + 0] = pack_bf16x2(f0 - h0, f1 - h1);
        fl_row[k2 + 1] = pack_bf16x2(f2 - h2, f3 - h3);
    }

    __syncthreads();

    // ---- Phase 2: per-warp m16n8k16 bf16 GEMM, 3-pass split ----
    const int warp = tid >> 5;
    const int lane = tid & 31;
    const int r = lane >> 2;          // 0..7
    const int c = lane & 3;           // 0..3

    float C[8][4];
    #pragma unroll
    for (int nt = 0; nt < 8; ++nt) {
        C[nt][0] = 0.f; C[nt][1] = 0.f; C[nt][2] = 0.f; C[nt][3] = 0.f;
    }

    const unsigned* AHb = FH + (warp * 16) * FSU;
    const unsigned* ALb = FL + (warp * 16) * FSU;
    #pragma unroll
    for (int kk = 0; kk < 4; ++kk) {
        int kb2 = kk * 8;                       // u32 (k-pair) base
        unsigned ah0 = AHb[r * FSU + kb2 + c];
        unsigned ah1 = AHb[(r + 8) * FSU + kb2 + c];
        unsigned ah2 = AHb[r * FSU + kb2 + c + 4];
        unsigned ah3 = AHb[(r + 8) * FSU + kb2 + c + 4];
        unsigned al0 = ALb[r * FSU + kb2 + c];
        unsigned al1 = ALb[(r + 8) * FSU + kb2 + c];
        unsigned al2 = ALb[r * FSU + kb2 + c + 4];
        unsigned al3 = ALb[(r + 8) * FSU + kb2 + c + 4];

        const unsigned* BH0 = BH + (kb2 + c) * WSU;
        const unsigned* BH4 = BH + (kb2 + c + 4) * WSU;
        const unsigned* BL0 = BL + (kb2 + c) * WSU;
        const unsigned* BL4 = BL + (kb2 + c + 4) * WSU;
        #pragma unroll
        for (int nt = 0; nt < 8; ++nt) {
            int n = nt * 8 + r;
            unsigned bh0 = BH0[n];
            unsigned bh1 = BH4[n];
            unsigned bl0 = BL0[n];
            unsigned bl1 = BL4[n];
            MMA_BF16(C[nt], ah0, ah1, ah2, ah3, bh0, bh1);
            MMA_BF16(C[nt], ah0, ah1, ah2, ah3, bl0, bl1);
            MMA_BF16(C[nt], al0, al1, al2, al3, bh0, bh1);
        }
    }

    // ---- Epilogue: softplus(h)·W1, reduce over c-lanes, density out ----
    float sig0 = 0.f, sig1 = 0.f;
    #pragma unroll
    for (int nt = 0; nt < 8; ++nt) {
        int col0 = nt * 8 + 2 * c;
        int col1 = col0 + 1;
        float b0a = sb0[col0], b0b = sb0[col1];
        float w1a = sW1[col0], w1b = sW1[col1];
        sig0 += softplus10(C[nt][0] + b0a) * w1a;
        sig0 += softplus10(C[nt][1] + b0b) * w1b;
        sig1 += softplus10(C[nt][2] + b0a) * w1a;
        sig1 += softplus10(C[nt][3] + b0b) * w1b;
    }
    sig0 += __shfl_xor_sync(0xffffffffu, sig0, 1);
    sig0 += __shfl_xor_sync(0xffffffffu, sig0, 2);
    sig1 += __shfl_xor_sync(0xffffffffu, sig1, 1);
    sig1 += __shfl_xor_sync(0xffffffffu, sig1, 2);

    if (c == 0) {
        float b1v = sb1[0];
        #pragma unroll
        for (int hrow = 0; hrow < 2; ++hrow) {
            int local = warp * 16 + r + hrow * 8;
            int pp = blockIdx.x * PTS + local;
            int rr = pp / TSAMP;
            int tt = pp - rr * TSAMP;
            float sigv  = (hrow == 0) ? sig0 : sig1;
            float sigma = softplus10(b1v + sigv);
            float zt  = step * (float)tt;
            float zt1 = step * (float)(tt - 1);
            float delta = (tt == 0) ? (1.0f / 192.0f) : (zt - zt1);
            out[pp] = delta * sigma;
        }
    }
}

extern "C" void kernel_launch(void* const* d_in, const int* in_sizes, int n_in,
                              void* d_out, int out_size) {
    const float* x   = (const float*)d_in[0];   // [4,2048,192,2]
    const float* emb = (const float*)d_in[1];   // [16, 524288, 4]
    const float* W0  = (const float*)d_in[2];   // [64,64]
    const float* b0  = (const float*)d_in[3];   // [64]
    const float* W1  = (const float*)d_in[4];   // [64,1]
    const float* b1  = (const float*)d_in[5];   // [1]
    float* out = (float*)d_out;

    LevelParams lp;
    const double b = exp((log(2048.0) - log(2.0)) / 15.0);
    unsigned mask = 0;
    for (int l = 0; l < NUM_LEVELS; ++l) {
        double s = 2.0 * pow(b, (double)l) - 1.0;
        lp.scale[l] = (float)s;
        int res = (int)ceil(s) + 1;
        lp.res[l] = res;
        if ((long long)res * (long long)res > (long long)TABLE_SIZE)
            mask |= (1u << l);
    }
    lp.hashed_mask = mask;

    const int smem_bytes = (2 * PTS * FSU + 2 * 32 * WSU) * 4 + (64 + 64 + 4) * 4;
    static int attr_set = 0;
    if (!attr_set) {
        cudaFuncSetAttribute(nerf_fused,
                             cudaFuncAttributeMaxDynamicSharedMemorySize,
                             smem_bytes);
        attr_set = 1;
    }

    int n_points = in_sizes[0] / 2;             // 1,572,864
    int n_blocks = n_points / PTS;              // 12288
    nerf_fused<<<n_blocks, NTHREADS, smem_bytes>>>(x, (const float4*)emb,
                                                   W0, b0, W1, b1, out, lp);
}